// round 1
// baseline (speedup 1.0000x reference)
#include <cuda_runtime.h>

// Problem shape (fixed by the dataset):
//   input  [4,10,5,384,384] f32  -> planes of HW, class-major inside each (n,t)
//   target [4,10,1,384,384] f32
//   weight [5] f32
#define HW      147456        // 384*384
#define HW4     36864         // HW/4
#define NT      40            // 4*10
#define TOTAL4  (NT * HW4)    // 1,474,560 float4 spatial items

#define NBLK 1184
#define NTHR 256

// Global accumulators (scratch; allocation-free per harness rules)
// [0..4] sumx, [5..8] A_i, [9..12] B_i, [13..16] c_i (threshold counts)
__device__ double g_acc[17];

__global__ void zero_k() {
    if (threadIdx.x < 17) g_acc[threadIdx.x] = 0.0;
}

__global__ void __launch_bounds__(NTHR) dice_main(
    const float4* __restrict__ x, const float4* __restrict__ t)
{
    float s0 = 0.f, s1 = 0.f, s2 = 0.f, s3 = 0.f, s4 = 0.f;
    float A0 = 0.f, A1 = 0.f, A2 = 0.f, A3 = 0.f;
    float B0 = 0.f, B1 = 0.f, B2 = 0.f, B3 = 0.f;
    int   c0 = 0, c1 = 0, c2 = 0, c3 = 0;

    const int stride = gridDim.x * blockDim.x;
    for (int i = blockIdx.x * blockDim.x + threadIdx.x; i < TOTAL4; i += stride) {
        const int nt = i / HW4;
        const int s4i = i - nt * HW4;
        const float4* xb = x + (size_t)nt * (5 * HW4) + s4i;

        const float4 xv0 = xb[0 * HW4];
        const float4 xv1 = xb[1 * HW4];
        const float4 xv2 = xb[2 * HW4];
        const float4 xv3 = xb[3 * HW4];
        const float4 xv4 = xb[4 * HW4];
        const float4 tv  = t[i];

        s0 += (xv0.x + xv0.y) + (xv0.z + xv0.w);
        s1 += (xv1.x + xv1.y) + (xv1.z + xv1.w);
        s2 += (xv2.x + xv2.y) + (xv2.z + xv2.w);
        s3 += (xv3.x + xv3.y) + (xv3.z + xv3.w);
        s4 += (xv4.x + xv4.y) + (xv4.z + xv4.w);

#define LANE(tj, a0, a1, a2, a3, a4)                                  \
        {                                                             \
            const bool p0 = (tj) >= 0.25f;                            \
            const bool p1 = (tj) >= 0.375f;                           \
            const bool p2 = (tj) >= 0.5f;                             \
            const bool p3 = (tj) >= 0.625f;                           \
            c0 += p0; c1 += p1; c2 += p2; c3 += p3;                   \
            if (p0) { A0 += (a0); B0 += (a1); }                       \
            if (p1) { A1 += (a1); B1 += (a2); }                       \
            if (p2) { A2 += (a2); B2 += (a3); }                       \
            if (p3) { A3 += (a3); B3 += (a4); }                       \
        }

        LANE(tv.x, xv0.x, xv1.x, xv2.x, xv3.x, xv4.x);
        LANE(tv.y, xv0.y, xv1.y, xv2.y, xv3.y, xv4.y);
        LANE(tv.z, xv0.z, xv1.z, xv2.z, xv3.z, xv4.z);
        LANE(tv.w, xv0.w, xv1.w, xv2.w, xv3.w, xv4.w);
#undef LANE
    }

    // ---- reduction: warp shuffle -> shared float -> global double atomics ----
    float vals[17] = { s0, s1, s2, s3, s4,
                       A0, A1, A2, A3,
                       B0, B1, B2, B3,
                       (float)c0, (float)c1, (float)c2, (float)c3 };

#pragma unroll
    for (int k = 0; k < 17; k++) {
#pragma unroll
        for (int o = 16; o > 0; o >>= 1)
            vals[k] += __shfl_down_sync(0xFFFFFFFFu, vals[k], o);
    }

    __shared__ float s_acc[17];
    if (threadIdx.x < 17) s_acc[threadIdx.x] = 0.f;
    __syncthreads();
    if ((threadIdx.x & 31) == 0) {
#pragma unroll
        for (int k = 0; k < 17; k++)
            atomicAdd(&s_acc[k], vals[k]);
    }
    __syncthreads();
    if (threadIdx.x < 17)
        atomicAdd(&g_acc[threadIdx.x], (double)s_acc[threadIdx.x]);
}

__global__ void finalize_k(const float* __restrict__ w, float* __restrict__ out,
                           double npos)
{
    if (threadIdx.x == 0 && blockIdx.x == 0) {
        double sum[5], A[4], B[4], c[4];
#pragma unroll
        for (int i = 0; i < 5; i++) sum[i] = g_acc[i];
#pragma unroll
        for (int i = 0; i < 4; i++) { A[i] = g_acc[5 + i]; B[i] = g_acc[9 + i]; c[i] = g_acc[13 + i]; }

        double cnt[5];
        cnt[0] = npos - c[0];
        cnt[1] = c[0] - c[1];
        cnt[2] = c[1] - c[2];
        cnt[3] = c[2] - c[3];
        cnt[4] = c[3];

        double inter[5];
        inter[0] = sum[0] - A[0];
        inter[1] = B[0] - A[1];
        inter[2] = B[1] - A[2];
        inter[3] = B[2] - A[3];
        inter[4] = B[3];

        const double S = 1e-5;
        double loss = 0.0;
#pragma unroll
        for (int cc = 0; cc < 5; cc++) {
            double dice = 1.0 - (2.0 * inter[cc] + S) / (sum[cc] + cnt[cc] + S);
            loss += (double)w[cc] * dice;
        }
        out[0] = (float)loss;
    }
}

extern "C" void kernel_launch(void* const* d_in, const int* in_sizes, int n_in,
                              void* d_out, int out_size)
{
    const float* x = (const float*)d_in[0];
    const float* t = (const float*)d_in[1];
    const float* w = (const float*)d_in[2];
    float* out = (float*)d_out;

    zero_k<<<1, 32>>>();
    dice_main<<<NBLK, NTHR>>>((const float4*)x, (const float4*)t);
    finalize_k<<<1, 32>>>(w, out, (double)in_sizes[1]);
}